// round 1
// baseline (speedup 1.0000x reference)
#include <cuda_runtime.h>
#include <math.h>

#define N_VEH 16
#define N_PED 16
#define DV 40
#define DP 24
#define NTOK 32
#define EE 128
#define NH 4
#define DH 32
#define OBS_DIM 1056
#define PITCH 132   // 128 + 4 pad, keeps rows 16B-aligned (132*4=528 bytes)

__global__ __launch_bounds__(128, 4)
void gnn_critic_kernel(const float* __restrict__ obs,
                       const float* __restrict__ Wv, const float* __restrict__ bv,
                       const float* __restrict__ Wp, const float* __restrict__ bp,
                       const float* __restrict__ w0, const float* __restrict__ asrc0, const float* __restrict__ adst0,
                       const float* __restrict__ w1, const float* __restrict__ asrc1, const float* __restrict__ adst1,
                       float* __restrict__ out)
{
    __shared__ float sx[NTOK][PITCH];   // current token features
    __shared__ float sh[NTOK][PITCH];   // h = x @ w
    __shared__ float sobs[OBS_DIM];
    __shared__ float salive[NTOK];
    __shared__ float s_as[NTOK][NH];
    __shared__ float s_ad[NTOK][NH];
    __shared__ float s_cnt;

    const int b = blockIdx.x;
    const int t = threadIdx.x;          // 0..127

    // ---- load per-batch observation into smem (coalesced) ----
    {
        const float* gobs = obs + (size_t)b * OBS_DIM;
        for (int i = t; i < OBS_DIM; i += 128) sobs[i] = gobs[i];
    }
    __syncthreads();

    // ---- alive mask + all-dead fix ----
    if (t < NTOK) salive[t] = (sobs[N_VEH*DV + N_PED*DP + t] >= 0.5f) ? 1.0f : 0.0f;
    __syncthreads();
    if (t == 0) {
        float s = 0.f;
        #pragma unroll
        for (int n = 0; n < NTOK; n++) s += salive[n];
        s_cnt = s;
    }
    __syncthreads();
    const bool all_dead = (s_cnt < 0.5f);
    if (all_dead && t < NTOK) salive[t] = 1.0f;
    const float cnt = all_dead ? (float)NTOK : s_cnt;   // >= 1, matches clip(sum,1)
    __syncthreads();

    // ---- token embedding: thread = output column c ----
    {
        const int c = t;
        float wcol[DV];
        #pragma unroll
        for (int k = 0; k < DV; k++) wcol[k] = Wv[k*EE + c];
        const float bvc = bv[c];
        #pragma unroll
        for (int n = 0; n < N_VEH; n++) {
            float acc = bvc;
            #pragma unroll
            for (int k = 0; k < DV; k++) acc += sobs[n*DV + k] * wcol[k];
            sx[n][c] = acc;
        }
        float wpcol[DP];
        #pragma unroll
        for (int k = 0; k < DP; k++) wpcol[k] = Wp[k*EE + c];
        const float bpc = bp[c];
        #pragma unroll
        for (int n = 0; n < N_PED; n++) {
            float acc = bpc;
            #pragma unroll
            for (int k = 0; k < DP; k++) acc += sobs[N_VEH*DV + n*DP + k] * wpcol[k];
            sx[N_VEH + n][c] = acc;
        }
    }
    __syncthreads();

    // ---- two GAT layers ----
    #pragma unroll 1
    for (int layer = 0; layer < 2; layer++) {
        const float* __restrict__ w  = layer ? w1    : w0;
        const float* __restrict__ as = layer ? asrc1 : asrc0;
        const float* __restrict__ ad = layer ? adst1 : adst0;

        // h = x @ w : thread = column c, 32 row-accumulators in registers
        {
            const int c = t;
            float acc[NTOK];
            #pragma unroll
            for (int n = 0; n < NTOK; n++) acc[n] = 0.f;
            #pragma unroll 1
            for (int k0 = 0; k0 < EE; k0 += 32) {
                float wr[32];
                #pragma unroll
                for (int kk = 0; kk < 32; kk++) wr[kk] = w[(k0 + kk)*EE + c];
                #pragma unroll
                for (int n = 0; n < NTOK; n++) {
                    float a = acc[n];
                    #pragma unroll
                    for (int q = 0; q < 8; q++) {
                        float4 xv = *(const float4*)&sx[n][k0 + q*4];
                        a += xv.x * wr[q*4+0];
                        a += xv.y * wr[q*4+1];
                        a += xv.z * wr[q*4+2];
                        a += xv.w * wr[q*4+3];
                    }
                    acc[n] = a;
                }
            }
            #pragma unroll
            for (int n = 0; n < NTOK; n++) sh[n][c] = acc[n];
        }
        __syncthreads();

        // alpha_src / alpha_dst : thread -> (node n, head hh)
        {
            const int n  = t >> 2;
            const int hh = t & 3;
            float a1 = 0.f, a2 = 0.f;
            #pragma unroll
            for (int d = 0; d < DH; d++) {
                float hv = sh[n][hh*DH + d];
                a1 += hv * as[hh*DH + d];
                a2 += hv * ad[hh*DH + d];
            }
            s_as[n][hh] = a1;
            s_ad[n][hh] = a2;
        }
        __syncthreads();

        // attention + apply + ELU : warp = head, lane = query i
        {
            const int hh = t >> 5;
            const int i  = t & 31;
            const float asi = s_as[i][hh];

            float ev[NTOK];
            float m = -1e30f;
            #pragma unroll
            for (int j = 0; j < NTOK; j++) {
                float v = asi + s_ad[j][hh];
                v = (v > 0.f) ? v : 0.2f * v;       // leaky relu BEFORE mask
                ev[j] = v;
                if (salive[j] >= 0.5f && v > m) m = v;
            }
            float psum = 0.f;
            #pragma unroll
            for (int j = 0; j < NTOK; j++) {
                float p = (salive[j] >= 0.5f) ? __expf(ev[j] - m) : 0.f;
                ev[j] = p;
                psum += p;
            }
            const float inv = 1.f / psum;

            // out[i, hh, d] = sum_j p_j * h[j, hh, d];  ELU; write into sx
            #pragma unroll
            for (int d0 = 0; d0 < DH; d0 += 4) {
                float a0 = 0.f, a1 = 0.f, a2 = 0.f, a3 = 0.f;
                #pragma unroll
                for (int j = 0; j < NTOK; j++) {
                    float4 hv = *(const float4*)&sh[j][hh*DH + d0];
                    const float p = ev[j];
                    a0 += p * hv.x;
                    a1 += p * hv.y;
                    a2 += p * hv.z;
                    a3 += p * hv.w;
                }
                a0 *= inv; a1 *= inv; a2 *= inv; a3 *= inv;
                a0 = (a0 > 0.f) ? a0 : expm1f(a0);
                a1 = (a1 > 0.f) ? a1 : expm1f(a1);
                a2 = (a2 > 0.f) ? a2 : expm1f(a2);
                a3 = (a3 > 0.f) ? a3 : expm1f(a3);
                sx[i][hh*DH + d0 + 0] = a0;
                sx[i][hh*DH + d0 + 1] = a1;
                sx[i][hh*DH + d0 + 2] = a2;
                sx[i][hh*DH + d0 + 3] = a3;
            }
        }
        __syncthreads();
    }

    // ---- masked mean pool: thread = column c ----
    {
        const int c = t;
        float acc = 0.f;
        #pragma unroll
        for (int n = 0; n < NTOK; n++) acc += sx[n][c] * salive[n];
        out[(size_t)b * EE + c] = acc / cnt;
    }
}

extern "C" void kernel_launch(void* const* d_in, const int* in_sizes, int n_in,
                              void* d_out, int out_size)
{
    const float* obs   = (const float*)d_in[0];
    const float* Wv    = (const float*)d_in[1];
    const float* bv    = (const float*)d_in[2];
    const float* Wp    = (const float*)d_in[3];
    const float* bp    = (const float*)d_in[4];
    const float* w0    = (const float*)d_in[5];
    const float* asrc0 = (const float*)d_in[6];
    const float* adst0 = (const float*)d_in[7];
    const float* w1    = (const float*)d_in[8];
    const float* asrc1 = (const float*)d_in[9];
    const float* adst1 = (const float*)d_in[10];
    float* out = (float*)d_out;

    const int B = in_sizes[0] / OBS_DIM;
    gnn_critic_kernel<<<B, 128>>>(obs, Wv, bv, Wp, bp,
                                  w0, asrc0, adst0, w1, asrc1, adst1, out);
}

// round 3
// speedup vs baseline: 1.9406x; 1.9406x over previous
#include <cuda_runtime.h>
#include <cstdint>
#include <math.h>

#define N_VEH 16
#define N_PED 16
#define NTOK 32
#define EE 128
#define NH 4
#define DH 32
#define OBS_DIM 1056
#define BPC 4
#define PITCH 132          // fp32 row pitch for sX/sH
#define BLKF 68            // floats per 8x8 fragment block (64 + 4 pad)

// float offsets in dynamic smem
#define F_SX    0                       // 128*132 = 16896
#define F_SH    16896                   // 128*132 = 16896
#define F_SW    33792                   // 256 blocks * 68 = 17408
#define F_BIAS  51200                   // 256
#define F_AS    51456                   // 512
#define F_AD    51968                   // 512
#define F_ALIVE 52480                   // 128
#define F_CNT   52608                   // 4
#define SMEM_FLOATS 52616
#define SMEM_BYTES (SMEM_FLOATS*4)

__device__ __forceinline__ uint32_t f2tf(float v) {
    uint32_t u; asm("cvt.rna.tf32.f32 %0, %1;" : "=r"(u) : "f"(v)); return u;
}

#define MMA8(c, a, bx, by) \
    asm volatile("mma.sync.aligned.m16n8k8.row.col.f32.tf32.tf32.f32 " \
        "{%0,%1,%2,%3}, {%4,%5,%6,%7}, {%8,%9}, {%0,%1,%2,%3};" \
        : "+f"((c)[0]), "+f"((c)[1]), "+f"((c)[2]), "+f"((c)[3]) \
        : "r"((a)[0]), "r"((a)[1]), "r"((a)[2]), "r"((a)[3]), "r"(bx), "r"(by))

__global__ __launch_bounds__(256, 1)
void gnn_mma_kernel(const float* __restrict__ obs,
                    const float* __restrict__ Wv, const float* __restrict__ bv,
                    const float* __restrict__ Wp, const float* __restrict__ bp,
                    const float* __restrict__ w0, const float* __restrict__ asrc0, const float* __restrict__ adst0,
                    const float* __restrict__ w1, const float* __restrict__ asrc1, const float* __restrict__ adst1,
                    float* __restrict__ out)
{
    extern __shared__ __align__(16) float sm[];
    float* sX     = sm + F_SX;
    float* sH     = sm + F_SH;
    float* sW     = sm + F_SW;
    float* sbias  = sm + F_BIAS;
    float* s_as   = sm + F_AS;
    float* s_ad   = sm + F_AD;
    float* salive = sm + F_ALIVE;
    float* scnt   = sm + F_CNT;

    const int t = threadIdx.x, wid = t >> 5, lane = t & 31;
    const int wr = wid >> 2, wc = wid & 3;      // warp tile: rows wr*64, cols wc*32
    const int qr = lane >> 2, qc = lane & 3;
    const int b0 = blockIdx.x * BPC;

    // ---- stage obs into sH (coalesced), biases ----
    {
        const float4* g4 = (const float4*)(obs + (size_t)b0 * OBS_DIM);
        float4* s4 = (float4*)sH;
        #pragma unroll
        for (int i = 0; i < BPC * OBS_DIM / 4 / 256 + 1; i++) {
            int idx = t + i * 256;
            if (idx < BPC * OBS_DIM / 4) s4[idx] = g4[idx];
        }
    }
    if (t < 128) { sbias[t] = bv[t]; sbias[128 + t] = bp[t]; }
    __syncthreads();

    // ---- alive + all-dead fix ----
    if (t < 128)
        salive[t] = (sH[(t >> 5) * OBS_DIM + 1024 + (t & 31)] >= 0.5f) ? 1.0f : 0.0f;
    __syncthreads();
    if (t < 4) {
        float s = 0.f;
        #pragma unroll
        for (int j = 0; j < 32; j++) s += salive[t * 32 + j];
        scnt[t] = s;
    }
    __syncthreads();
    if (t < 128 && scnt[t >> 5] < 0.5f) salive[t] = 1.0f;
    __syncthreads();
    if (t < 4 && scnt[t] < 0.5f) scnt[t] = 32.0f;

    // ---- stage embed A into sX [128 rows x 64 cols] (tf32-rounded) ----
    // row = be*32 + tok; tok<16: veh feats in cols 0..39; tok>=16: ped feats in cols 40..63
    #pragma unroll
    for (int i = 0; i < 32; i++) {
        int idx = t + i * 256;           // 128*64 = 8192
        int row = idx >> 6, c = idx & 63;
        int be = row >> 5, tok = row & 31;
        float v = 0.f;
        if (tok < 16) { if (c < 40) v = sH[be * OBS_DIM + tok * 40 + c]; }
        else          { if (c >= 40) v = sH[be * OBS_DIM + 640 + (tok - 16) * 24 + (c - 40)]; }
        sX[row * PITCH + c] = __uint_as_float(f2tf(v));
    }
    // ---- stage embed B = [Wv;Wp] (64 x 128) in fragment layout ----
    #pragma unroll
    for (int i = 0; i < 32; i++) {
        int idx = t + i * 256;           // 64*128 = 8192
        int k = idx >> 7, n = idx & 127;
        float v = (k < 40) ? Wv[k * EE + n] : Wp[(k - 40) * EE + n];
        int pos = ((k >> 3) * 16 + (n >> 3)) * BLKF + (n & 7) * 8 + (k & 3) * 2 + ((k >> 2) & 1);
        sW[pos] = __uint_as_float(f2tf(v));
    }
    __syncthreads();

    // ---- embed GEMM (K=64) ----
    {
        float acc[4][4][4];
        #pragma unroll
        for (int m = 0; m < 4; m++)
            #pragma unroll
            for (int n = 0; n < 4; n++)
                #pragma unroll
                for (int c = 0; c < 4; c++) acc[m][n][c] = 0.f;

        const float* Ab = sX + (wr * 64 + qr) * PITCH + qc;
        const float* Bb = sW + qr * 8 + qc * 2;
        #pragma unroll
        for (int k8 = 0; k8 < 8; k8++) {
            uint32_t Af[4][4];
            #pragma unroll
            for (int m = 0; m < 4; m++) {
                const float* p = Ab + m * 16 * PITCH + k8 * 8;
                Af[m][0] = __float_as_uint(p[0]);
                Af[m][1] = __float_as_uint(p[8 * PITCH]);
                Af[m][2] = __float_as_uint(p[4]);
                Af[m][3] = __float_as_uint(p[8 * PITCH + 4]);
            }
            #pragma unroll
            for (int n = 0; n < 4; n++) {
                uint2 bf = *(const uint2*)(Bb + (k8 * 16 + wc * 4 + n) * BLKF);
                #pragma unroll
                for (int m = 0; m < 4; m++) MMA8(acc[m][n], Af[m], bf.x, bf.y);
            }
        }
        __syncthreads();   // all warps done reading sX before overwrite

        // write embed output (+bias, tf32-rounded) into sX
        #pragma unroll
        for (int m = 0; m < 4; m++) {
            int row = wr * 64 + m * 16 + qr;
            const float* bb = ((row & 31) < 16) ? sbias : sbias + 128;
            #pragma unroll
            for (int n = 0; n < 4; n++) {
                int col = wc * 32 + n * 8 + qc * 2;
                sX[row * PITCH + col]           = __uint_as_float(f2tf(acc[m][n][0] + bb[col]));
                sX[row * PITCH + col + 1]       = __uint_as_float(f2tf(acc[m][n][1] + bb[col + 1]));
                sX[(row + 8) * PITCH + col]     = __uint_as_float(f2tf(acc[m][n][2] + bb[col]));
                sX[(row + 8) * PITCH + col + 1] = __uint_as_float(f2tf(acc[m][n][3] + bb[col + 1]));
            }
        }
    }

    // ---- two GAT layers ----
    for (int l = 0; l < 2; l++) {
        const float* w  = l ? w1 : w0;
        const float* as = l ? asrc1 : asrc0;
        const float* ad = l ? adst1 : adst0;

        // stage B = w (128x128) in fragment layout
        #pragma unroll
        for (int i = 0; i < 64; i++) {
            int idx = t + i * 256;
            int k = idx >> 7, n = idx & 127;
            int pos = ((k >> 3) * 16 + (n >> 3)) * BLKF + (n & 7) * 8 + (k & 3) * 2 + ((k >> 2) & 1);
            sW[pos] = __uint_as_float(f2tf(w[idx]));
        }
        __syncthreads();

        // GEMM: h = x @ w (K=128), output fp32 -> sH
        {
            float acc[4][4][4];
            #pragma unroll
            for (int m = 0; m < 4; m++)
                #pragma unroll
                for (int n = 0; n < 4; n++)
                    #pragma unroll
                    for (int c = 0; c < 4; c++) acc[m][n][c] = 0.f;

            const float* Ab = sX + (wr * 64 + qr) * PITCH + qc;
            const float* Bb = sW + qr * 8 + qc * 2;
            #pragma unroll
            for (int k8 = 0; k8 < 16; k8++) {
                uint32_t Af[4][4];
                #pragma unroll
                for (int m = 0; m < 4; m++) {
                    const float* p = Ab + m * 16 * PITCH + k8 * 8;
                    Af[m][0] = __float_as_uint(p[0]);
                    Af[m][1] = __float_as_uint(p[8 * PITCH]);
                    Af[m][2] = __float_as_uint(p[4]);
                    Af[m][3] = __float_as_uint(p[8 * PITCH + 4]);
                }
                #pragma unroll
                for (int n = 0; n < 4; n++) {
                    uint2 bf = *(const uint2*)(Bb + (k8 * 16 + wc * 4 + n) * BLKF);
                    #pragma unroll
                    for (int m = 0; m < 4; m++) MMA8(acc[m][n], Af[m], bf.x, bf.y);
                }
            }
            #pragma unroll
            for (int m = 0; m < 4; m++) {
                int row = wr * 64 + m * 16 + qr;
                #pragma unroll
                for (int n = 0; n < 4; n++) {
                    int col = wc * 32 + n * 8 + qc * 2;
                    *(float2*)&sH[row * PITCH + col]       = make_float2(acc[m][n][0], acc[m][n][1]);
                    *(float2*)&sH[(row + 8) * PITCH + col] = make_float2(acc[m][n][2], acc[m][n][3]);
                }
            }
        }
        __syncthreads();

        // alpha_src / alpha_dst : 512 (row,head) pairs
        #pragma unroll
        for (int it = 0; it < 2; it++) {
            int idx = t + it * 256;
            int gr = idx >> 2, hh = idx & 3;
            const float* pas = as + hh * 32;
            const float* pad_ = ad + hh * 32;
            float a1 = 0.f, a2 = 0.f;
            #pragma unroll
            for (int d = 0; d < 32; d++) {
                float hv = sH[gr * PITCH + hh * 32 + d];
                a1 += hv * pas[d];
                a2 += hv * pad_[d];
            }
            s_as[idx] = a1;
            s_ad[idx] = a2;
        }
        __syncthreads();

        // attention + apply + ELU : task = (be, head), lane = query i
        #pragma unroll
        for (int it = 0; it < 2; it++) {
            int task = wid + it * 8;
            int be = task >> 2, hh = task & 3;
            int i = lane;
            int gri = be * 32 + i;
            float asi = s_as[gri * 4 + hh];
            const float* alv = salive + be * 32;

            float ev[32];
            float mx = -1e30f;
            #pragma unroll
            for (int j = 0; j < 32; j++) {
                float e = asi + s_ad[(be * 32 + j) * 4 + hh];
                e = (e > 0.f) ? e : 0.2f * e;
                ev[j] = e;
                if (alv[j] >= 0.5f && e > mx) mx = e;
            }
            float ps = 0.f;
            #pragma unroll
            for (int j = 0; j < 32; j++) {
                float p = (alv[j] >= 0.5f) ? __expf(ev[j] - mx) : 0.f;
                ev[j] = p;
                ps += p;
            }
            float inv = 1.f / ps;

            if (l == 0) {
                #pragma unroll
                for (int d0 = 0; d0 < 32; d0 += 4) {
                    float a0 = 0.f, a1 = 0.f, a2 = 0.f, a3 = 0.f;
                    #pragma unroll
                    for (int j = 0; j < 32; j++) {
                        float4 hv = *(const float4*)&sH[(be * 32 + j) * PITCH + hh * 32 + d0];
                        float p = ev[j];
                        a0 += p * hv.x; a1 += p * hv.y; a2 += p * hv.z; a3 += p * hv.w;
                    }
                    a0 *= inv; a1 *= inv; a2 *= inv; a3 *= inv;
                    a0 = (a0 > 0.f) ? a0 : expm1f(a0);
                    a1 = (a1 > 0.f) ? a1 : expm1f(a1);
                    a2 = (a2 > 0.f) ? a2 : expm1f(a2);
                    a3 = (a3 > 0.f) ? a3 : expm1f(a3);
                    sX[gri * PITCH + hh * 32 + d0 + 0] = __uint_as_float(f2tf(a0));
                    sX[gri * PITCH + hh * 32 + d0 + 1] = __uint_as_float(f2tf(a1));
                    sX[gri * PITCH + hh * 32 + d0 + 2] = __uint_as_float(f2tf(a2));
                    sX[gri * PITCH + hh * 32 + d0 + 3] = __uint_as_float(f2tf(a3));
                }
            } else {
                float wi = alv[i];
                float invc = 1.f / scnt[be];
                float keep = 0.f;
                #pragma unroll
                for (int d0 = 0; d0 < 32; d0 += 4) {
                    float a0 = 0.f, a1 = 0.f, a2 = 0.f, a3 = 0.f;
                    #pragma unroll
                    for (int j = 0; j < 32; j++) {
                        float4 hv = *(const float4*)&sH[(be * 32 + j) * PITCH + hh * 32 + d0];
                        float p = ev[j];
                        a0 += p * hv.x; a1 += p * hv.y; a2 += p * hv.z; a3 += p * hv.w;
                    }
                    a0 *= inv; a1 *= inv; a2 *= inv; a3 *= inv;
                    a0 = (a0 > 0.f) ? a0 : expm1f(a0);
                    a1 = (a1 > 0.f) ? a1 : expm1f(a1);
                    a2 = (a2 > 0.f) ? a2 : expm1f(a2);
                    a3 = (a3 > 0.f) ? a3 : expm1f(a3);
                    float vals[4] = {a0, a1, a2, a3};
                    #pragma unroll
                    for (int q = 0; q < 4; q++) {
                        float r = vals[q] * wi;
                        r += __shfl_xor_sync(0xffffffffu, r, 16);
                        r += __shfl_xor_sync(0xffffffffu, r, 8);
                        r += __shfl_xor_sync(0xffffffffu, r, 4);
                        r += __shfl_xor_sync(0xffffffffu, r, 2);
                        r += __shfl_xor_sync(0xffffffffu, r, 1);
                        if (lane == d0 + q) keep = r;
                    }
                }
                out[(size_t)(b0 + be) * EE + hh * 32 + lane] = keep * invc;
            }
        }
        __syncthreads();
    }
}

extern "C" void kernel_launch(void* const* d_in, const int* in_sizes, int n_in,
                              void* d_out, int out_size)
{
    const float* obs   = (const float*)d_in[0];
    const float* Wv    = (const float*)d_in[1];
    const float* bv    = (const float*)d_in[2];
    const float* Wp    = (const float*)d_in[3];
    const float* bp    = (const float*)d_in[4];
    const float* w0    = (const float*)d_in[5];
    const float* asrc0 = (const float*)d_in[6];
    const float* adst0 = (const float*)d_in[7];
    const float* w1    = (const float*)d_in[8];
    const float* asrc1 = (const float*)d_in[9];
    const float* adst1 = (const float*)d_in[10];
    float* out = (float*)d_out;

    const int B = in_sizes[0] / OBS_DIM;
    cudaFuncSetAttribute(gnn_mma_kernel, cudaFuncAttributeMaxDynamicSharedMemorySize, SMEM_BYTES);
    gnn_mma_kernel<<<B / BPC, 256, SMEM_BYTES>>>(obs, Wv, bv, Wp, bp,
                                                 w0, asrc0, adst0, w1, asrc1, adst1, out);
}

// round 4
// speedup vs baseline: 2.9711x; 1.5310x over previous
#include <cuda_runtime.h>
#include <cstdint>
#include <math.h>

#define N_VEH 16
#define N_PED 16
#define NTOK 32
#define EE 128
#define NH 4
#define DH 32
#define OBS_DIM 1056
#define BPC 4
#define NTHR 512
#define PITCH 132          // fp32 row pitch for sX/sH
#define BLKF 68            // floats per 8x8 fragment block (64 + 4 pad)

// float offsets in dynamic smem
#define F_SX    0                       // 128*132 = 16896
#define F_SH    16896                   // 128*132 = 16896
#define F_SW    33792                   // 256 blocks * 68 = 17408
#define F_BIAS  51200                   // 256
#define F_AS    51456                   // 512
#define F_AD    51968                   // 512
#define F_ALIVE 52480                   // 128
#define F_CNT   52608                   // 4
#define SMEM_FLOATS 52616
#define SMEM_BYTES (SMEM_FLOATS*4)

__device__ __forceinline__ uint32_t f2tf(float v) {
    uint32_t u; asm("cvt.rna.tf32.f32 %0, %1;" : "=r"(u) : "f"(v)); return u;
}

#define MMA8(c, a, bx, by) \
    asm volatile("mma.sync.aligned.m16n8k8.row.col.f32.tf32.tf32.f32 " \
        "{%0,%1,%2,%3}, {%4,%5,%6,%7}, {%8,%9}, {%0,%1,%2,%3};" \
        : "+f"((c)[0]), "+f"((c)[1]), "+f"((c)[2]), "+f"((c)[3]) \
        : "r"((a)[0]), "r"((a)[1]), "r"((a)[2]), "r"((a)[3]), "r"(bx), "r"(by))

__global__ __launch_bounds__(NTHR, 1)
void gnn_mma_kernel(const float* __restrict__ obs,
                    const float* __restrict__ Wv, const float* __restrict__ bv,
                    const float* __restrict__ Wp, const float* __restrict__ bp,
                    const float* __restrict__ w0, const float* __restrict__ asrc0, const float* __restrict__ adst0,
                    const float* __restrict__ w1, const float* __restrict__ asrc1, const float* __restrict__ adst1,
                    float* __restrict__ out)
{
    extern __shared__ __align__(16) float sm[];
    float* sX     = sm + F_SX;
    float* sH     = sm + F_SH;
    float* sW     = sm + F_SW;
    float* sbias  = sm + F_BIAS;
    float* s_as   = sm + F_AS;
    float* s_ad   = sm + F_AD;
    float* salive = sm + F_ALIVE;
    float* scnt   = sm + F_CNT;

    const int t = threadIdx.x, wid = t >> 5, lane = t & 31;
    const int wr = wid >> 2, wc = wid & 3;      // warp tile: rows wr*32, cols wc*32
    const int qr = lane >> 2, qc = lane & 3;
    const int b0 = blockIdx.x * BPC;

    // ---- stage obs into sH (coalesced), biases ----
    {
        const float4* g4 = (const float4*)(obs + (size_t)b0 * OBS_DIM);
        float4* s4 = (float4*)sH;
        #pragma unroll
        for (int i = 0; i < 3; i++) {
            int idx = t + i * NTHR;
            if (idx < BPC * OBS_DIM / 4) s4[idx] = g4[idx];
        }
    }
    if (t < 128) { sbias[t] = bv[t]; sbias[128 + t] = bp[t]; }
    __syncthreads();

    // ---- alive + all-dead fix ----
    if (t < 128)
        salive[t] = (sH[(t >> 5) * OBS_DIM + 1024 + (t & 31)] >= 0.5f) ? 1.0f : 0.0f;
    __syncthreads();
    if (t < 4) {
        float s = 0.f;
        #pragma unroll
        for (int j = 0; j < 32; j++) s += salive[t * 32 + j];
        scnt[t] = s;
    }
    __syncthreads();
    if (t < 128 && scnt[t >> 5] < 0.5f) salive[t] = 1.0f;
    __syncthreads();
    if (t < 4 && scnt[t] < 0.5f) scnt[t] = 32.0f;

    // ---- stage embed A into sX [128 rows x 64 cols] (tf32-rounded) ----
    #pragma unroll
    for (int i = 0; i < 16; i++) {
        int idx = t + i * NTHR;          // 128*64 = 8192
        int row = idx >> 6, c = idx & 63;
        int be = row >> 5, tok = row & 31;
        float v = 0.f;
        if (tok < 16) { if (c < 40) v = sH[be * OBS_DIM + tok * 40 + c]; }
        else          { if (c >= 40) v = sH[be * OBS_DIM + 640 + (tok - 16) * 24 + (c - 40)]; }
        sX[row * PITCH + c] = __uint_as_float(f2tf(v));
    }
    // ---- stage embed B = [Wv;Wp] (64 x 128) in fragment layout ----
    #pragma unroll
    for (int i = 0; i < 16; i++) {
        int idx = t + i * NTHR;          // 64*128 = 8192
        int k = idx >> 7, n = idx & 127;
        float v = (k < 40) ? Wv[k * EE + n] : Wp[(k - 40) * EE + n];
        int pos = ((k >> 3) * 16 + (n >> 3)) * BLKF + (n & 7) * 8 + (k & 3) * 2 + ((k >> 2) & 1);
        sW[pos] = __uint_as_float(f2tf(v));
    }
    __syncthreads();

    // ---- embed GEMM (K=64), warp tile 32x32 ----
    {
        float acc[2][4][4];
        #pragma unroll
        for (int m = 0; m < 2; m++)
            #pragma unroll
            for (int n = 0; n < 4; n++)
                #pragma unroll
                for (int c = 0; c < 4; c++) acc[m][n][c] = 0.f;

        const float* Ab = sX + (wr * 32 + qr) * PITCH + qc;
        const float* Bb = sW + qr * 8 + qc * 2;
        #pragma unroll
        for (int k8 = 0; k8 < 8; k8++) {
            uint32_t Af[2][4];
            #pragma unroll
            for (int m = 0; m < 2; m++) {
                const float* p = Ab + m * 16 * PITCH + k8 * 8;
                Af[m][0] = __float_as_uint(p[0]);
                Af[m][1] = __float_as_uint(p[8 * PITCH]);
                Af[m][2] = __float_as_uint(p[4]);
                Af[m][3] = __float_as_uint(p[8 * PITCH + 4]);
            }
            #pragma unroll
            for (int n = 0; n < 4; n++) {
                uint2 bf = *(const uint2*)(Bb + (k8 * 16 + wc * 4 + n) * BLKF);
                #pragma unroll
                for (int m = 0; m < 2; m++) MMA8(acc[m][n], Af[m], bf.x, bf.y);
            }
        }
        __syncthreads();   // all warps done reading sX/sW before overwrite

        // write embed output (+bias, tf32-rounded) into sX
        #pragma unroll
        for (int m = 0; m < 2; m++) {
            int row = wr * 32 + m * 16 + qr;
            const float* bb = ((row & 31) < 16) ? sbias : sbias + 128;
            #pragma unroll
            for (int n = 0; n < 4; n++) {
                int col = wc * 32 + n * 8 + qc * 2;
                sX[row * PITCH + col]           = __uint_as_float(f2tf(acc[m][n][0] + bb[col]));
                sX[row * PITCH + col + 1]       = __uint_as_float(f2tf(acc[m][n][1] + bb[col + 1]));
                sX[(row + 8) * PITCH + col]     = __uint_as_float(f2tf(acc[m][n][2] + bb[col]));
                sX[(row + 8) * PITCH + col + 1] = __uint_as_float(f2tf(acc[m][n][3] + bb[col + 1]));
            }
        }
    }

    // ---- two GAT layers ----
    for (int l = 0; l < 2; l++) {
        const float* w  = l ? w1 : w0;
        const float* as = l ? asrc1 : asrc0;
        const float* ad = l ? adst1 : adst0;

        // stage B = w (128x128) in fragment layout
        #pragma unroll
        for (int i = 0; i < 32; i++) {
            int idx = t + i * NTHR;
            int k = idx >> 7, n = idx & 127;
            int pos = ((k >> 3) * 16 + (n >> 3)) * BLKF + (n & 7) * 8 + (k & 3) * 2 + ((k >> 2) & 1);
            sW[pos] = __uint_as_float(f2tf(w[idx]));
        }
        __syncthreads();

        // GEMM: h = x @ w (K=128), output fp32 -> sH
        {
            float acc[2][4][4];
            #pragma unroll
            for (int m = 0; m < 2; m++)
                #pragma unroll
                for (int n = 0; n < 4; n++)
                    #pragma unroll
                    for (int c = 0; c < 4; c++) acc[m][n][c] = 0.f;

            const float* Ab = sX + (wr * 32 + qr) * PITCH + qc;
            const float* Bb = sW + qr * 8 + qc * 2;
            #pragma unroll
            for (int k8 = 0; k8 < 16; k8++) {
                uint32_t Af[2][4];
                #pragma unroll
                for (int m = 0; m < 2; m++) {
                    const float* p = Ab + m * 16 * PITCH + k8 * 8;
                    Af[m][0] = __float_as_uint(p[0]);
                    Af[m][1] = __float_as_uint(p[8 * PITCH]);
                    Af[m][2] = __float_as_uint(p[4]);
                    Af[m][3] = __float_as_uint(p[8 * PITCH + 4]);
                }
                #pragma unroll
                for (int n = 0; n < 4; n++) {
                    uint2 bf = *(const uint2*)(Bb + (k8 * 16 + wc * 4 + n) * BLKF);
                    #pragma unroll
                    for (int m = 0; m < 2; m++) MMA8(acc[m][n], Af[m], bf.x, bf.y);
                }
            }
            #pragma unroll
            for (int m = 0; m < 2; m++) {
                int row = wr * 32 + m * 16 + qr;
                #pragma unroll
                for (int n = 0; n < 4; n++) {
                    int col = wc * 32 + n * 8 + qc * 2;
                    *(float2*)&sH[row * PITCH + col]       = make_float2(acc[m][n][0], acc[m][n][1]);
                    *(float2*)&sH[(row + 8) * PITCH + col] = make_float2(acc[m][n][2], acc[m][n][3]);
                }
            }
        }
        __syncthreads();

        // alpha_src / alpha_dst : 512 (row,head) pairs, 1 per thread
        {
            int gr = t >> 2, hh = t & 3;
            const float* pas = as + hh * 32;
            const float* pad_ = ad + hh * 32;
            float a1 = 0.f, a2 = 0.f;
            #pragma unroll
            for (int d = 0; d < 32; d++) {
                float hv = sH[gr * PITCH + hh * 32 + d];
                a1 += hv * pas[d];
                a2 += hv * pad_[d];
            }
            s_as[t] = a1;
            s_ad[t] = a2;
        }
        __syncthreads();

        // attention + apply + ELU : warp = (be, head) task, lane = query i
        {
            int be = wid >> 2, hh = wid & 3;
            int i = lane;
            int gri = be * 32 + i;
            float asi = s_as[gri * 4 + hh];
            const float* alv = salive + be * 32;

            float ev[32];
            float mx = -1e30f;
            #pragma unroll
            for (int j = 0; j < 32; j++) {
                float e = asi + s_ad[(be * 32 + j) * 4 + hh];
                e = (e > 0.f) ? e : 0.2f * e;
                ev[j] = e;
                if (alv[j] >= 0.5f && e > mx) mx = e;
            }
            float ps = 0.f;
            #pragma unroll
            for (int j = 0; j < 32; j++) {
                float p = (alv[j] >= 0.5f) ? __expf(ev[j] - mx) : 0.f;
                ev[j] = p;
                ps += p;
            }
            float inv = 1.f / ps;

            if (l == 0) {
                #pragma unroll
                for (int d0 = 0; d0 < 32; d0 += 4) {
                    float a0 = 0.f, a1 = 0.f, a2 = 0.f, a3 = 0.f;
                    #pragma unroll
                    for (int j = 0; j < 32; j++) {
                        float4 hv = *(const float4*)&sH[(be * 32 + j) * PITCH + hh * 32 + d0];
                        float p = ev[j];
                        a0 += p * hv.x; a1 += p * hv.y; a2 += p * hv.z; a3 += p * hv.w;
                    }
                    a0 *= inv; a1 *= inv; a2 *= inv; a3 *= inv;
                    a0 = (a0 > 0.f) ? a0 : expm1f(a0);
                    a1 = (a1 > 0.f) ? a1 : expm1f(a1);
                    a2 = (a2 > 0.f) ? a2 : expm1f(a2);
                    a3 = (a3 > 0.f) ? a3 : expm1f(a3);
                    sX[gri * PITCH + hh * 32 + d0 + 0] = __uint_as_float(f2tf(a0));
                    sX[gri * PITCH + hh * 32 + d0 + 1] = __uint_as_float(f2tf(a1));
                    sX[gri * PITCH + hh * 32 + d0 + 2] = __uint_as_float(f2tf(a2));
                    sX[gri * PITCH + hh * 32 + d0 + 3] = __uint_as_float(f2tf(a3));
                }
            } else {
                float wi = alv[i];
                float invc = 1.f / scnt[be];
                float keep = 0.f;
                #pragma unroll
                for (int d0 = 0; d0 < 32; d0 += 4) {
                    float a0 = 0.f, a1 = 0.f, a2 = 0.f, a3 = 0.f;
                    #pragma unroll
                    for (int j = 0; j < 32; j++) {
                        float4 hv = *(const float4*)&sH[(be * 32 + j) * PITCH + hh * 32 + d0];
                        float p = ev[j];
                        a0 += p * hv.x; a1 += p * hv.y; a2 += p * hv.z; a3 += p * hv.w;
                    }
                    a0 *= inv; a1 *= inv; a2 *= inv; a3 *= inv;
                    a0 = (a0 > 0.f) ? a0 : expm1f(a0);
                    a1 = (a1 > 0.f) ? a1 : expm1f(a1);
                    a2 = (a2 > 0.f) ? a2 : expm1f(a2);
                    a3 = (a3 > 0.f) ? a3 : expm1f(a3);
                    float vals[4] = {a0, a1, a2, a3};
                    #pragma unroll
                    for (int q = 0; q < 4; q++) {
                        float r = vals[q] * wi;
                        r += __shfl_xor_sync(0xffffffffu, r, 16);
                        r += __shfl_xor_sync(0xffffffffu, r, 8);
                        r += __shfl_xor_sync(0xffffffffu, r, 4);
                        r += __shfl_xor_sync(0xffffffffu, r, 2);
                        r += __shfl_xor_sync(0xffffffffu, r, 1);
                        if (lane == d0 + q) keep = r;
                    }
                }
                out[(size_t)(b0 + be) * EE + hh * 32 + lane] = keep * invc;
            }
        }
        __syncthreads();
    }
}

extern "C" void kernel_launch(void* const* d_in, const int* in_sizes, int n_in,
                              void* d_out, int out_size)
{
    const float* obs   = (const float*)d_in[0];
    const float* Wv    = (const float*)d_in[1];
    const float* bv    = (const float*)d_in[2];
    const float* Wp    = (const float*)d_in[3];
    const float* bp    = (const float*)d_in[4];
    const float* w0    = (const float*)d_in[5];
    const float* asrc0 = (const float*)d_in[6];
    const float* adst0 = (const float*)d_in[7];
    const float* w1    = (const float*)d_in[8];
    const float* asrc1 = (const float*)d_in[9];
    const float* adst1 = (const float*)d_in[10];
    float* out = (float*)d_out;

    const int B = in_sizes[0] / OBS_DIM;
    cudaFuncSetAttribute(gnn_mma_kernel, cudaFuncAttributeMaxDynamicSharedMemorySize, SMEM_BYTES);
    gnn_mma_kernel<<<B / BPC, NTHR, SMEM_BYTES>>>(obs, Wv, bv, Wp, bp,
                                                  w0, asrc0, adst0, w1, asrc1, adst1, out);
}

// round 5
// speedup vs baseline: 3.6060x; 1.2137x over previous
#include <cuda_runtime.h>
#include <cstdint>
#include <math.h>

#define N_VEH 16
#define N_PED 16
#define NTOK 32
#define EE 128
#define NH 4
#define DH 32
#define OBS_DIM 1056
#define BPC 2
#define NTHR 256
#define MROWS 64           // BPC*NTOK
#define PITCH 132          // fp32 row pitch

// fragment-layout weight buffers (tf32 bit patterns stored as float)
__device__ float g_efrag[8 * 16 * 64];       // embed B: K=64 (8 k8-blocks) x 128
__device__ float g_wfrag[2][16 * 16 * 64];   // w0, w1: K=128 x 128

// smem float offsets
#define F_SX    0                    // 64*132 = 8448
#define F_SH    8448                 // 64*132 = 8448
#define F_AS    16896                // 256
#define F_AD    17152                // 256
#define F_ALIVE 17408                // 64
#define F_CNT   17472                // 4
#define SMEM_FLOATS 17480
#define SMEM_BYTES (SMEM_FLOATS*4)

__device__ __forceinline__ uint32_t f2tf(float v) {
    uint32_t u; asm("cvt.rna.tf32.f32 %0, %1;" : "=r"(u) : "f"(v)); return u;
}

#define FRAG_POS(k, n) ((((k) >> 3) * 16 + ((n) >> 3)) * 64 + ((n) & 7) * 8 + ((k) & 3) * 2 + (((k) >> 2) & 1))

#define MMA8(c, a, bx, by) \
    asm volatile("mma.sync.aligned.m16n8k8.row.col.f32.tf32.tf32.f32 " \
        "{%0,%1,%2,%3}, {%4,%5,%6,%7}, {%8,%9}, {%0,%1,%2,%3};" \
        : "+f"((c)[0]), "+f"((c)[1]), "+f"((c)[2]), "+f"((c)[3]) \
        : "r"((a)[0]), "r"((a)[1]), "r"((a)[2]), "r"((a)[3]), "r"(bx), "r"(by))

// ---- prologue: convert weights to tf32 fragment layout ----
__global__ void conv_weights(const float* __restrict__ Wv, const float* __restrict__ Wp,
                             const float* __restrict__ w0, const float* __restrict__ w1)
{
    int t = blockIdx.x * blockDim.x + threadIdx.x;   // 0..40959
    if (t < 8192) {
        int k = t >> 7, n = t & 127;
        float v = (k < 40) ? Wv[k * EE + n] : Wp[(k - 40) * EE + n];
        g_efrag[FRAG_POS(k, n)] = __uint_as_float(f2tf(v));
    } else {
        int u = t - 8192;
        int l = u >> 14; u &= 16383;
        int k = u >> 7, n = u & 127;
        const float* w = l ? w1 : w0;
        g_wfrag[l][FRAG_POS(k, n)] = __uint_as_float(f2tf(w[u]));
    }
}

__global__ __launch_bounds__(NTHR, 3)
void gnn_mma_kernel(const float* __restrict__ obs,
                    const float* __restrict__ bv, const float* __restrict__ bp,
                    const float* __restrict__ asrc0, const float* __restrict__ adst0,
                    const float* __restrict__ asrc1, const float* __restrict__ adst1,
                    float* __restrict__ out)
{
    extern __shared__ __align__(16) float sm[];
    float* sX     = sm + F_SX;
    float* sH     = sm + F_SH;
    float* s_as   = sm + F_AS;
    float* s_ad   = sm + F_AD;
    float* salive = sm + F_ALIVE;
    float* scnt   = sm + F_CNT;

    const int t = threadIdx.x, wid = t >> 5, lane = t & 31;
    const int wr = wid >> 2, wc = wid & 3;      // warp tile rows wr*32, cols wc*32
    const int qr = lane >> 2, qc = lane & 3;
    const int b0 = blockIdx.x * BPC;

    // ---- stage obs (2 rows) into sH ----
    {
        const float4* g4 = (const float4*)(obs + (size_t)b0 * OBS_DIM);
        float4* s4 = (float4*)sH;
        #pragma unroll
        for (int i = 0; i < 3; i++) {
            int idx = t + i * NTHR;
            if (idx < BPC * OBS_DIM / 4) s4[idx] = g4[idx];
        }
    }
    __syncthreads();

    // ---- alive + all-dead fix ----
    if (t < MROWS)
        salive[t] = (sH[(t >> 5) * OBS_DIM + 1024 + (t & 31)] >= 0.5f) ? 1.0f : 0.0f;
    __syncthreads();
    if (t < BPC) {
        float s = 0.f;
        #pragma unroll
        for (int j = 0; j < 32; j++) s += salive[t * 32 + j];
        scnt[t] = s;
    }
    __syncthreads();
    if (t < MROWS && scnt[t >> 5] < 0.5f) salive[t] = 1.0f;
    __syncthreads();
    if (t < BPC && scnt[t] < 0.5f) scnt[t] = 32.0f;

    // ---- stage embed A into sX [64 x 64] ----
    #pragma unroll
    for (int i = 0; i < 16; i++) {
        int idx = t + i * NTHR;          // 64*64 = 4096
        int row = idx >> 6, c = idx & 63;
        int be = row >> 5, tok = row & 31;
        float v = 0.f;
        if (tok < 16) { if (c < 40) v = sH[be * OBS_DIM + tok * 40 + c]; }
        else          { if (c >= 40) v = sH[be * OBS_DIM + 640 + (tok - 16) * 24 + (c - 40)]; }
        sX[row * PITCH + c] = __uint_as_float(f2tf(v));
    }
    __syncthreads();

    // ---- embed GEMM (K=64) ----
    {
        float acc[2][4][4];
        #pragma unroll
        for (int m = 0; m < 2; m++)
            #pragma unroll
            for (int n = 0; n < 4; n++)
                #pragma unroll
                for (int c = 0; c < 4; c++) acc[m][n][c] = 0.f;

        const float* Ab = sX + (wr * 32 + qr) * PITCH + qc;
        const float* Bg = g_efrag + (wc * 4) * 64 + qr * 8 + qc * 2;

        uint2 bf[4];
        #pragma unroll
        for (int n = 0; n < 4; n++) bf[n] = *(const uint2*)(Bg + n * 64);

        #pragma unroll
        for (int k8 = 0; k8 < 8; k8++) {
            uint2 nf[4];
            if (k8 < 7) {
                #pragma unroll
                for (int n = 0; n < 4; n++)
                    nf[n] = *(const uint2*)(Bg + ((k8 + 1) * 16 + n) * 64);
            }
            uint32_t Af[2][4];
            #pragma unroll
            for (int m = 0; m < 2; m++) {
                const float* p = Ab + m * 16 * PITCH + k8 * 8;
                Af[m][0] = __float_as_uint(p[0]);
                Af[m][1] = __float_as_uint(p[8 * PITCH]);
                Af[m][2] = __float_as_uint(p[4]);
                Af[m][3] = __float_as_uint(p[8 * PITCH + 4]);
            }
            #pragma unroll
            for (int n = 0; n < 4; n++)
                #pragma unroll
                for (int m = 0; m < 2; m++) MMA8(acc[m][n], Af[m], bf[n].x, bf[n].y);
            #pragma unroll
            for (int n = 0; n < 4; n++) bf[n] = nf[n];
        }
        __syncthreads();   // done reading sX before overwrite

        // write embed output (+bias, tf32) into sX
        #pragma unroll
        for (int m = 0; m < 2; m++) {
            int row = wr * 32 + m * 16 + qr;
            const float* bb = ((row & 31) < 16) ? bv : bp;
            #pragma unroll
            for (int n = 0; n < 4; n++) {
                int col = wc * 32 + n * 8 + qc * 2;
                sX[row * PITCH + col]           = __uint_as_float(f2tf(acc[m][n][0] + bb[col]));
                sX[row * PITCH + col + 1]       = __uint_as_float(f2tf(acc[m][n][1] + bb[col + 1]));
                sX[(row + 8) * PITCH + col]     = __uint_as_float(f2tf(acc[m][n][2] + bb[col]));
                sX[(row + 8) * PITCH + col + 1] = __uint_as_float(f2tf(acc[m][n][3] + bb[col + 1]));
            }
        }
    }
    __syncthreads();

    // ---- two GAT layers ----
    for (int l = 0; l < 2; l++) {
        const float* gw = g_wfrag[l];
        const float* as = l ? asrc1 : asrc0;
        const float* ad = l ? adst1 : adst0;

        // GEMM: h = x @ w (K=128) -> sH (fp32)
        {
            float acc[2][4][4];
            #pragma unroll
            for (int m = 0; m < 2; m++)
                #pragma unroll
                for (int n = 0; n < 4; n++)
                    #pragma unroll
                    for (int c = 0; c < 4; c++) acc[m][n][c] = 0.f;

            const float* Ab = sX + (wr * 32 + qr) * PITCH + qc;
            const float* Bg = gw + (wc * 4) * 64 + qr * 8 + qc * 2;

            uint2 bf[4];
            #pragma unroll
            for (int n = 0; n < 4; n++) bf[n] = *(const uint2*)(Bg + n * 64);

            #pragma unroll
            for (int k8 = 0; k8 < 16; k8++) {
                uint2 nf[4];
                if (k8 < 15) {
                    #pragma unroll
                    for (int n = 0; n < 4; n++)
                        nf[n] = *(const uint2*)(Bg + ((k8 + 1) * 16 + n) * 64);
                }
                uint32_t Af[2][4];
                #pragma unroll
                for (int m = 0; m < 2; m++) {
                    const float* p = Ab + m * 16 * PITCH + k8 * 8;
                    Af[m][0] = __float_as_uint(p[0]);
                    Af[m][1] = __float_as_uint(p[8 * PITCH]);
                    Af[m][2] = __float_as_uint(p[4]);
                    Af[m][3] = __float_as_uint(p[8 * PITCH + 4]);
                }
                #pragma unroll
                for (int n = 0; n < 4; n++)
                    #pragma unroll
                    for (int m = 0; m < 2; m++) MMA8(acc[m][n], Af[m], bf[n].x, bf[n].y);
                #pragma unroll
                for (int n = 0; n < 4; n++) bf[n] = nf[n];
            }
            #pragma unroll
            for (int m = 0; m < 2; m++) {
                int row = wr * 32 + m * 16 + qr;
                #pragma unroll
                for (int n = 0; n < 4; n++) {
                    int col = wc * 32 + n * 8 + qc * 2;
                    *(float2*)&sH[row * PITCH + col]       = make_float2(acc[m][n][0], acc[m][n][1]);
                    *(float2*)&sH[(row + 8) * PITCH + col] = make_float2(acc[m][n][2], acc[m][n][3]);
                }
            }
        }
        __syncthreads();

        // alpha_src / alpha_dst : 256 (row,head) pairs, 1/thread
        {
            int gr = t >> 2, hh = t & 3;
            const float* pas = as + hh * 32;
            const float* pad_ = ad + hh * 32;
            float a1 = 0.f, a2 = 0.f;
            #pragma unroll
            for (int d = 0; d < 32; d++) {
                float hv = sH[gr * PITCH + hh * 32 + d];
                a1 += hv * pas[d];
                a2 += hv * pad_[d];
            }
            s_as[t] = a1;
            s_ad[t] = a2;
        }
        __syncthreads();

        // attention + apply + ELU : warp = (be, head) task, lane = query i
        {
            int be = wid >> 2, hh = wid & 3;
            int i = lane;
            int gri = be * 32 + i;
            float asi = s_as[gri * 4 + hh];
            const float* alv = salive + be * 32;

            float ev[32];
            float mx = -1e30f;
            #pragma unroll
            for (int j = 0; j < 32; j++) {
                float e = asi + s_ad[(be * 32 + j) * 4 + hh];
                e = (e > 0.f) ? e : 0.2f * e;
                ev[j] = e;
                if (alv[j] >= 0.5f && e > mx) mx = e;
            }
            float ps = 0.f;
            #pragma unroll
            for (int j = 0; j < 32; j++) {
                float p = (alv[j] >= 0.5f) ? __expf(ev[j] - mx) : 0.f;
                ev[j] = p;
                ps += p;
            }
            float inv = 1.f / ps;

            if (l == 0) {
                #pragma unroll
                for (int d0 = 0; d0 < 32; d0 += 4) {
                    float a0 = 0.f, a1 = 0.f, a2 = 0.f, a3 = 0.f;
                    #pragma unroll
                    for (int j = 0; j < 32; j++) {
                        float4 hv = *(const float4*)&sH[(be * 32 + j) * PITCH + hh * 32 + d0];
                        float p = ev[j];
                        a0 += p * hv.x; a1 += p * hv.y; a2 += p * hv.z; a3 += p * hv.w;
                    }
                    a0 *= inv; a1 *= inv; a2 *= inv; a3 *= inv;
                    a0 = (a0 > 0.f) ? a0 : expm1f(a0);
                    a1 = (a1 > 0.f) ? a1 : expm1f(a1);
                    a2 = (a2 > 0.f) ? a2 : expm1f(a2);
                    a3 = (a3 > 0.f) ? a3 : expm1f(a3);
                    sX[gri * PITCH + hh * 32 + d0 + 0] = __uint_as_float(f2tf(a0));
                    sX[gri * PITCH + hh * 32 + d0 + 1] = __uint_as_float(f2tf(a1));
                    sX[gri * PITCH + hh * 32 + d0 + 2] = __uint_as_float(f2tf(a2));
                    sX[gri * PITCH + hh * 32 + d0 + 3] = __uint_as_float(f2tf(a3));
                }
            } else {
                float wi = alv[i];
                float invc = 1.f / scnt[be];
                float keep = 0.f;
                #pragma unroll
                for (int d0 = 0; d0 < 32; d0 += 4) {
                    float a0 = 0.f, a1 = 0.f, a2 = 0.f, a3 = 0.f;
                    #pragma unroll
                    for (int j = 0; j < 32; j++) {
                        float4 hv = *(const float4*)&sH[(be * 32 + j) * PITCH + hh * 32 + d0];
                        float p = ev[j];
                        a0 += p * hv.x; a1 += p * hv.y; a2 += p * hv.z; a3 += p * hv.w;
                    }
                    a0 *= inv; a1 *= inv; a2 *= inv; a3 *= inv;
                    a0 = (a0 > 0.f) ? a0 : expm1f(a0);
                    a1 = (a1 > 0.f) ? a1 : expm1f(a1);
                    a2 = (a2 > 0.f) ? a2 : expm1f(a2);
                    a3 = (a3 > 0.f) ? a3 : expm1f(a3);
                    float vals[4] = {a0, a1, a2, a3};
                    #pragma unroll
                    for (int q = 0; q < 4; q++) {
                        float r = vals[q] * wi;
                        r += __shfl_xor_sync(0xffffffffu, r, 16);
                        r += __shfl_xor_sync(0xffffffffu, r, 8);
                        r += __shfl_xor_sync(0xffffffffu, r, 4);
                        r += __shfl_xor_sync(0xffffffffu, r, 2);
                        r += __shfl_xor_sync(0xffffffffu, r, 1);
                        if (lane == d0 + q) keep = r;
                    }
                }
                out[(size_t)(b0 + be) * EE + hh * 32 + lane] = keep * invc;
            }
        }
        __syncthreads();
    }
}

extern "C" void kernel_launch(void* const* d_in, const int* in_sizes, int n_in,
                              void* d_out, int out_size)
{
    const float* obs   = (const float*)d_in[0];
    const float* Wv    = (const float*)d_in[1];
    const float* bv    = (const float*)d_in[2];
    const float* Wp    = (const float*)d_in[3];
    const float* bp    = (const float*)d_in[4];
    const float* w0    = (const float*)d_in[5];
    const float* asrc0 = (const float*)d_in[6];
    const float* adst0 = (const float*)d_in[7];
    const float* w1    = (const float*)d_in[8];
    const float* asrc1 = (const float*)d_in[9];
    const float* adst1 = (const float*)d_in[10];
    float* out = (float*)d_out;

    const int B = in_sizes[0] / OBS_DIM;

    conv_weights<<<160, 256>>>(Wv, Wp, w0, w1);
    cudaFuncSetAttribute(gnn_mma_kernel, cudaFuncAttributeMaxDynamicSharedMemorySize, SMEM_BYTES);
    gnn_mma_kernel<<<B / BPC, NTHR, SMEM_BYTES>>>(obs, bv, bp,
                                                  asrc0, adst0, asrc1, adst1, out);
}

// round 6
// speedup vs baseline: 4.2552x; 1.1800x over previous
#include <cuda_runtime.h>
#include <cstdint>
#include <math.h>

#define N_VEH 16
#define N_PED 16
#define NTOK 32
#define EE 128
#define NH 4
#define DH 32
#define OBS_DIM 1056
#define BPC 2
#define NTHR 256
#define MROWS 64           // BPC*NTOK
#define PITCH 132          // fp32 row pitch

// fragment-layout weight buffers (tf32 bit patterns stored as float)
__device__ float g_efrag[8 * 16 * 64];       // embed B: K=64 (8 k8-blocks) x 128
__device__ float g_wfrag[2][16 * 16 * 64];   // w0, w1: K=128 x 128

// smem float offsets
#define F_SX    0                    // 64*132 = 8448
#define F_SH    8448                 // 64*132 = 8448
#define F_AS    16896                // 256
#define F_AD    17152                // 256
#define F_ALIVE 17408                // 64
#define F_CNT   17472                // 4
#define SMEM_FLOATS 17480
#define SMEM_BYTES (SMEM_FLOATS*4)

__device__ __forceinline__ uint32_t f2tf(float v) {
    uint32_t u; asm("cvt.rna.tf32.f32 %0, %1;" : "=r"(u) : "f"(v)); return u;
}

#define FRAG_POS(k, n) ((((k) >> 3) * 16 + ((n) >> 3)) * 64 + ((n) & 7) * 8 + ((k) & 3) * 2 + (((k) >> 2) & 1))

#define MMA8(c, a, bx, by) \
    asm volatile("mma.sync.aligned.m16n8k8.row.col.f32.tf32.tf32.f32 " \
        "{%0,%1,%2,%3}, {%4,%5,%6,%7}, {%8,%9}, {%0,%1,%2,%3};" \
        : "+f"((c)[0]), "+f"((c)[1]), "+f"((c)[2]), "+f"((c)[3]) \
        : "r"((a)[0]), "r"((a)[1]), "r"((a)[2]), "r"((a)[3]), "r"(bx), "r"(by))

// ---- prologue: convert weights to tf32 fragment layout ----
__global__ void conv_weights(const float* __restrict__ Wv, const float* __restrict__ Wp,
                             const float* __restrict__ w0, const float* __restrict__ w1)
{
    int t = blockIdx.x * blockDim.x + threadIdx.x;   // 0..40959
    if (t < 8192) {
        int k = t >> 7, n = t & 127;
        float v = (k < 40) ? Wv[k * EE + n] : Wp[(k - 40) * EE + n];
        g_efrag[FRAG_POS(k, n)] = __uint_as_float(f2tf(v));
    } else {
        int u = t - 8192;
        int l = u >> 14; u &= 16383;
        int k = u >> 7, n = u & 127;
        const float* w = l ? w1 : w0;
        g_wfrag[l][FRAG_POS(k, n)] = __uint_as_float(f2tf(w[u]));
    }
}

__global__ __launch_bounds__(NTHR, 3)
void gnn_mma_kernel(const float* __restrict__ obs,
                    const float* __restrict__ bv, const float* __restrict__ bp,
                    const float* __restrict__ asrc0, const float* __restrict__ adst0,
                    const float* __restrict__ asrc1, const float* __restrict__ adst1,
                    float* __restrict__ out)
{
    extern __shared__ __align__(16) float sm[];
    float* sX     = sm + F_SX;
    float* sH     = sm + F_SH;
    float* s_as   = sm + F_AS;
    float* s_ad   = sm + F_AD;
    float* salive = sm + F_ALIVE;
    float* scnt   = sm + F_CNT;

    const int t = threadIdx.x, wid = t >> 5, lane = t & 31;
    const int wr = wid >> 2, wc = wid & 3;      // GEMM warp tile rows wr*32, cols wc*32
    const int qr = lane >> 2, qc = lane & 3;
    const int b0 = blockIdx.x * BPC;

    // ---- stage obs (2 rows) into sH ----
    {
        const float4* g4 = (const float4*)(obs + (size_t)b0 * OBS_DIM);
        float4* s4 = (float4*)sH;
        #pragma unroll
        for (int i = 0; i < 3; i++) {
            int idx = t + i * NTHR;
            if (idx < BPC * OBS_DIM / 4) s4[idx] = g4[idx];
        }
    }
    __syncthreads();

    // ---- alive + all-dead fix ----
    if (t < MROWS)
        salive[t] = (sH[(t >> 5) * OBS_DIM + 1024 + (t & 31)] >= 0.5f) ? 1.0f : 0.0f;
    __syncthreads();
    if (t < BPC) {
        float s = 0.f;
        #pragma unroll
        for (int j = 0; j < 32; j++) s += salive[t * 32 + j];
        scnt[t] = s;
    }
    __syncthreads();
    if (t < MROWS && scnt[t >> 5] < 0.5f) salive[t] = 1.0f;
    __syncthreads();
    if (t < BPC && scnt[t] < 0.5f) scnt[t] = 32.0f;

    // ---- stage embed A into sX [64 x 64] ----
    #pragma unroll
    for (int i = 0; i < 16; i++) {
        int idx = t + i * NTHR;          // 64*64 = 4096
        int row = idx >> 6, c = idx & 63;
        int be = row >> 5, tok = row & 31;
        float v = 0.f;
        if (tok < 16) { if (c < 40) v = sH[be * OBS_DIM + tok * 40 + c]; }
        else          { if (c >= 40) v = sH[be * OBS_DIM + 640 + (tok - 16) * 24 + (c - 40)]; }
        sX[row * PITCH + c] = __uint_as_float(f2tf(v));
    }
    __syncthreads();

    // ---- embed GEMM (K=64) ----
    {
        float acc[2][4][4];
        #pragma unroll
        for (int m = 0; m < 2; m++)
            #pragma unroll
            for (int n = 0; n < 4; n++)
                #pragma unroll
                for (int c = 0; c < 4; c++) acc[m][n][c] = 0.f;

        const float* Ab = sX + (wr * 32 + qr) * PITCH + qc;
        const float* Bg = g_efrag + (wc * 4) * 64 + qr * 8 + qc * 2;

        uint2 bf[4];
        #pragma unroll
        for (int n = 0; n < 4; n++) bf[n] = *(const uint2*)(Bg + n * 64);

        #pragma unroll
        for (int k8 = 0; k8 < 8; k8++) {
            uint2 nf[4];
            if (k8 < 7) {
                #pragma unroll
                for (int n = 0; n < 4; n++)
                    nf[n] = *(const uint2*)(Bg + ((k8 + 1) * 16 + n) * 64);
            }
            uint32_t Af[2][4];
            #pragma unroll
            for (int m = 0; m < 2; m++) {
                const float* p = Ab + m * 16 * PITCH + k8 * 8;
                Af[m][0] = __float_as_uint(p[0]);
                Af[m][1] = __float_as_uint(p[8 * PITCH]);
                Af[m][2] = __float_as_uint(p[4]);
                Af[m][3] = __float_as_uint(p[8 * PITCH + 4]);
            }
            #pragma unroll
            for (int n = 0; n < 4; n++)
                #pragma unroll
                for (int m = 0; m < 2; m++) MMA8(acc[m][n], Af[m], bf[n].x, bf[n].y);
            #pragma unroll
            for (int n = 0; n < 4; n++) bf[n] = nf[n];
        }
        __syncthreads();   // done reading sX before overwrite

        // write embed output (+bias, tf32) into sX
        #pragma unroll
        for (int m = 0; m < 2; m++) {
            int row = wr * 32 + m * 16 + qr;
            const float* bb = ((row & 31) < 16) ? bv : bp;
            #pragma unroll
            for (int n = 0; n < 4; n++) {
                int col = wc * 32 + n * 8 + qc * 2;
                sX[row * PITCH + col]           = __uint_as_float(f2tf(acc[m][n][0] + bb[col]));
                sX[row * PITCH + col + 1]       = __uint_as_float(f2tf(acc[m][n][1] + bb[col + 1]));
                sX[(row + 8) * PITCH + col]     = __uint_as_float(f2tf(acc[m][n][2] + bb[col]));
                sX[(row + 8) * PITCH + col + 1] = __uint_as_float(f2tf(acc[m][n][3] + bb[col + 1]));
            }
        }
    }
    __syncthreads();

    // ---- two GAT layers ----
    for (int l = 0; l < 2; l++) {
        const float* gw = g_wfrag[l];
        const float* as = l ? asrc1 : asrc0;
        const float* ad = l ? adst1 : adst0;

        // GEMM: h = x @ w (K=128) -> sH (fp32)
        {
            float acc[2][4][4];
            #pragma unroll
            for (int m = 0; m < 2; m++)
                #pragma unroll
                for (int n = 0; n < 4; n++)
                    #pragma unroll
                    for (int c = 0; c < 4; c++) acc[m][n][c] = 0.f;

            const float* Ab = sX + (wr * 32 + qr) * PITCH + qc;
            const float* Bg = gw + (wc * 4) * 64 + qr * 8 + qc * 2;

            uint2 bf[4];
            #pragma unroll
            for (int n = 0; n < 4; n++) bf[n] = *(const uint2*)(Bg + n * 64);

            #pragma unroll
            for (int k8 = 0; k8 < 16; k8++) {
                uint2 nf[4];
                if (k8 < 15) {
                    #pragma unroll
                    for (int n = 0; n < 4; n++)
                        nf[n] = *(const uint2*)(Bg + ((k8 + 1) * 16 + n) * 64);
                }
                uint32_t Af[2][4];
                #pragma unroll
                for (int m = 0; m < 2; m++) {
                    const float* p = Ab + m * 16 * PITCH + k8 * 8;
                    Af[m][0] = __float_as_uint(p[0]);
                    Af[m][1] = __float_as_uint(p[8 * PITCH]);
                    Af[m][2] = __float_as_uint(p[4]);
                    Af[m][3] = __float_as_uint(p[8 * PITCH + 4]);
                }
                #pragma unroll
                for (int n = 0; n < 4; n++)
                    #pragma unroll
                    for (int m = 0; m < 2; m++) MMA8(acc[m][n], Af[m], bf[n].x, bf[n].y);
                #pragma unroll
                for (int n = 0; n < 4; n++) bf[n] = nf[n];
            }
            #pragma unroll
            for (int m = 0; m < 2; m++) {
                int row = wr * 32 + m * 16 + qr;
                #pragma unroll
                for (int n = 0; n < 4; n++) {
                    int col = wc * 32 + n * 8 + qc * 2;
                    *(float2*)&sH[row * PITCH + col]       = make_float2(acc[m][n][0], acc[m][n][1]);
                    *(float2*)&sH[(row + 8) * PITCH + col] = make_float2(acc[m][n][2], acc[m][n][3]);
                }
            }
        }
        __syncthreads();

        // alpha_src / alpha_dst : 256 (row,head) pairs, 1/thread (float4 loads)
        {
            int gr = t >> 2, hh = t & 3;
            const float* pas = as + hh * 32;
            const float* pad_ = ad + hh * 32;
            float a1 = 0.f, a2 = 0.f;
            #pragma unroll
            for (int d0 = 0; d0 < 32; d0 += 4) {
                float4 hv = *(const float4*)&sH[gr * PITCH + hh * 32 + d0];
                a1 += hv.x * pas[d0] + hv.y * pas[d0+1] + hv.z * pas[d0+2] + hv.w * pas[d0+3];
                a2 += hv.x * pad_[d0] + hv.y * pad_[d0+1] + hv.z * pad_[d0+2] + hv.w * pad_[d0+3];
            }
            s_as[t] = a1;
            s_ad[t] = a2;
        }
        __syncthreads();

        // ---- attention: softmax -> P into sX scratch -> tensor-core apply ----
        {
            const int be = wid >> 2, hh = wid & 3;
            const int i = lane;
            const int gri = be * 32 + i;
            const float asi = s_as[gri * 4 + hh];
            const float* alv = salive + be * 32;

            float ev[32];
            float mx = -1e30f;
            #pragma unroll
            for (int j = 0; j < 32; j++) {
                float e = asi + s_ad[(be * 32 + j) * 4 + hh];
                e = (e > 0.f) ? e : 0.2f * e;
                ev[j] = e;
                if (alv[j] >= 0.5f && e > mx) mx = e;
            }
            float ps = 0.f;
            #pragma unroll
            for (int j = 0; j < 32; j++) {
                float p = (alv[j] >= 0.5f) ? __expf(ev[j] - mx) : 0.f;
                ev[j] = p;
                ps += p;
            }
            const float inv = 1.f / ps;

            // store normalized P (tf32) into sX block [be*32.., hh*32..] (this warp's own O region)
            float* Prow = sX + gri * PITCH + hh * 32;
            #pragma unroll
            for (int j = 0; j < 32; j += 4) {
                float4 pv;
                pv.x = __uint_as_float(f2tf(ev[j] * inv));
                pv.y = __uint_as_float(f2tf(ev[j+1] * inv));
                pv.z = __uint_as_float(f2tf(ev[j+2] * inv));
                pv.w = __uint_as_float(f2tf(ev[j+3] * inv));
                *(float4*)&Prow[j] = pv;
            }
            __syncwarp();

            // O = P @ Hd  (M=32,N=32,K=32) via 2x4x4 m16n8k8
            float acc[2][4][4];
            #pragma unroll
            for (int m = 0; m < 2; m++)
                #pragma unroll
                for (int n = 0; n < 4; n++)
                    #pragma unroll
                    for (int c = 0; c < 4; c++) acc[m][n][c] = 0.f;

            const float* Pb = sX + (be * 32 + qr) * PITCH + hh * 32 + qc;
            const float* Hb = sH + (be * 32 + qc) * PITCH + hh * 32 + qr;
            #pragma unroll
            for (int k8 = 0; k8 < 4; k8++) {
                uint32_t Af[2][4];
                #pragma unroll
                for (int m = 0; m < 2; m++) {
                    const float* p = Pb + m * 16 * PITCH + k8 * 8;
                    Af[m][0] = __float_as_uint(p[0]);
                    Af[m][1] = __float_as_uint(p[8 * PITCH]);
                    Af[m][2] = __float_as_uint(p[4]);
                    Af[m][3] = __float_as_uint(p[8 * PITCH + 4]);
                }
                const float* hb = Hb + k8 * 8 * PITCH;
                #pragma unroll
                for (int n = 0; n < 4; n++) {
                    uint32_t bx = f2tf(hb[n * 8]);
                    uint32_t by = f2tf(hb[4 * PITCH + n * 8]);
                    #pragma unroll
                    for (int m = 0; m < 2; m++) MMA8(acc[m][n], Af[m], bx, by);
                }
            }

            if (l == 0) {
                // ELU -> tf32 -> overwrite own P block with O
                #pragma unroll
                for (int m = 0; m < 2; m++) {
                    int row = be * 32 + m * 16 + qr;
                    #pragma unroll
                    for (int n = 0; n < 4; n++) {
                        int col = hh * 32 + n * 8 + qc * 2;
                        float a0 = acc[m][n][0], a1 = acc[m][n][1];
                        float a2 = acc[m][n][2], a3 = acc[m][n][3];
                        a0 = (a0 > 0.f) ? a0 : expm1f(a0);
                        a1 = (a1 > 0.f) ? a1 : expm1f(a1);
                        a2 = (a2 > 0.f) ? a2 : expm1f(a2);
                        a3 = (a3 > 0.f) ? a3 : expm1f(a3);
                        sX[row * PITCH + col]           = __uint_as_float(f2tf(a0));
                        sX[row * PITCH + col + 1]       = __uint_as_float(f2tf(a1));
                        sX[(row + 8) * PITCH + col]     = __uint_as_float(f2tf(a2));
                        sX[(row + 8) * PITCH + col + 1] = __uint_as_float(f2tf(a3));
                    }
                }
            } else {
                // fused ELU + alive-weighted pooling
                const float invc = 1.f / scnt[be];
                float aw[2][2];
                #pragma unroll
                for (int m = 0; m < 2; m++) {
                    aw[m][0] = alv[m * 16 + qr];
                    aw[m][1] = alv[m * 16 + qr + 8];
                }
                #pragma unroll
                for (int n = 0; n < 4; n++) {
                    #pragma unroll
                    for (int c = 0; c < 2; c++) {
                        float s = 0.f;
                        #pragma unroll
                        for (int m = 0; m < 2; m++) {
                            float v0 = acc[m][n][c];
                            float v1 = acc[m][n][2 + c];
                            v0 = (v0 > 0.f) ? v0 : expm1f(v0);
                            v1 = (v1 > 0.f) ? v1 : expm1f(v1);
                            s += aw[m][0] * v0 + aw[m][1] * v1;
                        }
                        s += __shfl_xor_sync(0xffffffffu, s, 4);
                        s += __shfl_xor_sync(0xffffffffu, s, 8);
                        s += __shfl_xor_sync(0xffffffffu, s, 16);
                        if (qr == 0)
                            out[(size_t)(b0 + be) * EE + hh * 32 + n * 8 + qc * 2 + c] = s * invc;
                    }
                }
            }
        }
        __syncthreads();
    }
}

extern "C" void kernel_launch(void* const* d_in, const int* in_sizes, int n_in,
                              void* d_out, int out_size)
{
    const float* obs   = (const float*)d_in[0];
    const float* Wv    = (const float*)d_in[1];
    const float* bv    = (const float*)d_in[2];
    const float* Wp    = (const float*)d_in[3];
    const float* bp    = (const float*)d_in[4];
    const float* w0    = (const float*)d_in[5];
    const float* asrc0 = (const float*)d_in[6];
    const float* adst0 = (const float*)d_in[7];
    const float* w1    = (const float*)d_in[8];
    const float* asrc1 = (const float*)d_in[9];
    const float* adst1 = (const float*)d_in[10];
    float* out = (float*)d_out;

    const int B = in_sizes[0] / OBS_DIM;

    conv_weights<<<160, 256>>>(Wv, Wp, w0, w1);
    cudaFuncSetAttribute(gnn_mma_kernel, cudaFuncAttributeMaxDynamicSharedMemorySize, SMEM_BYTES);
    gnn_mma_kernel<<<B / BPC, NTHR, SMEM_BYTES>>>(obs, bv, bp,
                                                  asrc0, adst0, asrc1, adst1, out);
}